// round 4
// baseline (speedup 1.0000x reference)
#include <cuda_runtime.h>
#include <cstdint>
#include <math.h>

#define N_NODES 100000
#define N_EDGES 3200000
#define D_FEAT 64
#define NUM_RELS 20
#define HID_ATTR 32
#define OUT_ATTR 10

#define NSEG (NUM_RELS * N_NODES)          // 2,000,000 segments (r*N + dst)
#define SCAN_CHUNK 1024
#define SC_BLOCKS ((NSEG + SCAN_CHUNK - 1) / SCAN_CHUNK)   // 1954
#define SCAN_PAD (SC_BLOCKS * SCAN_CHUNK)

// ---------------- scratch (device globals; no allocation allowed) ----------------
__device__ float g_H1[(size_t)N_NODES * D_FEAT];             // hidden layer output
__device__ int   g_cnt[NSEG];
__device__ int   g_fill[NSEG];
__device__ int   g_rowptr[NSEG + 1];
__device__ int   g_scan[SCAN_PAD];
__device__ int   g_bsums[SC_BLOCKS];
__device__ int   g_boff[SC_BLOCKS];
__device__ int   g_eidx[N_EDGES];                            // sorted by (etype,dst): src node id
__device__ float g_sum[D_FEAT];                              // column sums of h2

__device__ __forceinline__ uint32_t f2tf32(float x) {
    uint32_t r; asm("cvt.rna.tf32.f32 %0, %1;" : "=r"(r) : "f"(x)); return r;
}

// ---------------- CSR build kernels ----------------
__global__ void k_zero() {
    int i = blockIdx.x * blockDim.x + threadIdx.x;
    if (i < NSEG) { g_cnt[i] = 0; g_fill[i] = 0; }
    if (blockIdx.x == 0 && threadIdx.x < D_FEAT) g_sum[threadIdx.x] = 0.0f;
}

__global__ void k_count(const int* __restrict__ dst, const int* __restrict__ etype) {
    int e = blockIdx.x * blockDim.x + threadIdx.x;
    if (e < N_EDGES) atomicAdd(&g_cnt[etype[e] * N_NODES + dst[e]], 1);
}

__global__ void k_scan1() {
    __shared__ int sm[256];
    int t = threadIdx.x;
    int base = blockIdx.x * SCAN_CHUNK;
    int v[4];
    int local = 0;
#pragma unroll
    for (int c = 0; c < 4; c++) {
        int idx = base + t * 4 + c;
        v[c] = (idx < NSEG) ? g_cnt[idx] : 0;
        local += v[c];
    }
    sm[t] = local;
    __syncthreads();
    for (int off = 1; off < 256; off <<= 1) {
        int x = sm[t];
        int y = (t >= off) ? sm[t - off] : 0;
        __syncthreads();
        sm[t] = x + y;
        __syncthreads();
    }
    int run = sm[t] - local;
#pragma unroll
    for (int c = 0; c < 4; c++) {
        run += v[c];
        g_scan[base + t * 4 + c] = run;   // inclusive within chunk
    }
    if (t == 255) g_bsums[blockIdx.x] = sm[255];
}

// scan 1954 block sums with one 1024-thread block (2 elems/thread, ping-pong HS)
__global__ void k_scan2() {
    __shared__ int a[1024], b[1024];
    int t = threadIdx.x;
    int v0 = (2 * t     < SC_BLOCKS) ? g_bsums[2 * t]     : 0;
    int v1 = (2 * t + 1 < SC_BLOCKS) ? g_bsums[2 * t + 1] : 0;
    int pair = v0 + v1;
    a[t] = pair;
    __syncthreads();
    int* cur = a; int* nxt = b;
    for (int off = 1; off < 1024; off <<= 1) {
        int x = cur[t];
        if (t >= off) x += cur[t - off];
        nxt[t] = x;
        __syncthreads();
        int* tmp = cur; cur = nxt; nxt = tmp;
    }
    int excl_pair = cur[t] - pair;     // exclusive scan of pair sums
    if (2 * t     < SC_BLOCKS) g_boff[2 * t]     = excl_pair;
    if (2 * t + 1 < SC_BLOCKS) g_boff[2 * t + 1] = excl_pair + v0;
}

__global__ void k_scan3() {
    int i = blockIdx.x * blockDim.x + threadIdx.x;
    if (i < NSEG) g_rowptr[i + 1] = g_scan[i] + g_boff[i >> 10];
    if (i == 0) g_rowptr[0] = 0;
}

__global__ void k_fill(const int* __restrict__ src, const int* __restrict__ dst,
                       const int* __restrict__ etype) {
    int e = blockIdx.x * blockDim.x + threadIdx.x;
    if (e < N_EDGES) {
        int key = etype[e] * N_NODES + dst[e];
        int pos = g_rowptr[key] + atomicAdd(&g_fill[key], 1);
        g_eidx[pos] = src[e];
    }
}

// ---------------- fused layer: out[v] = act( sum_r (sum_{e in r->v} X[src]) @ W[r] )
// CTA = 128 dst nodes; accumulator kept in registers across all 20 relations.
#define AS_STRIDE 68
#define AS_WORDS (128 * AS_STRIDE)          // 34816 B
#define WS_STRIDE 72
#define WS_WORDS (64 * WS_STRIDE)           // 18432 B
#define FU_SMEM ((AS_WORDS + WS_WORDS) * 4) // 53248 B

template <bool RELU>
__global__ void __launch_bounds__(256) k_fused(const float* __restrict__ X,
                                               const float* __restrict__ W,
                                               float* __restrict__ out) {
    extern __shared__ float smf[];
    float*    As = smf;                            // f32  [128][68]
    uint32_t* Ws = (uint32_t*)(smf + AS_WORDS);    // tf32 [64][72]

    const int tid = threadIdx.x;
    const int wid = tid >> 5;
    const int lane = tid & 31;
    const int g = lane >> 2;             // groupID 0..7
    const int t4 = lane & 3;             // thread-in-group 0..3
    const int m0 = blockIdx.x * 128;
    const int base = m0 + wid * 16;      // this warp's 16 dst nodes

    float c[8][4];
#pragma unroll
    for (int nt = 0; nt < 8; nt++) { c[nt][0] = 0.f; c[nt][1] = 0.f; c[nt][2] = 0.f; c[nt][3] = 0.f; }

    for (int r = 0; r < NUM_RELS; r++) {
        if (r) __syncthreads();          // prior MMA frag reads done; safe to overwrite tiles

        // stage W[r] as tf32 [k][n] (B col-major for row.col mma)
        const float* Wr = W + (size_t)r * 4096;
#pragma unroll
        for (int i = 0; i < 4; i++) {
            int f = i * 256 + tid;       // float4 slot 0..1023
            int krow = f >> 4;
            int n4 = (f & 15) << 2;
            float4 v = *(const float4*)(Wr + krow * 64 + n4);
            uint4 u;
            u.x = f2tf32(v.x); u.y = f2tf32(v.y); u.z = f2tf32(v.z); u.w = f2tf32(v.w);
            *(uint4*)(Ws + krow * WS_STRIDE + n4) = u;
        }

        // cooperative rowptr load for 17 boundaries of this warp's 16 nodes
        int rp = 0;
        {
            int node = base + lane;
            int nclamp = node < N_NODES ? node : N_NODES;
            if (lane < 17) rp = g_rowptr[r * N_NODES + nclamp];
        }

        // aggregate: node j's row = sum of h[src] over its relation-r edges
        for (int j = 0; j < 16; j++) {
            int v = base + j;
            int s = __shfl_sync(0xffffffffu, rp, j);
            int e = __shfl_sync(0xffffffffu, rp, j + 1);
            float2 acc = make_float2(0.f, 0.f);
            if (v < N_NODES) {
#pragma unroll 4
                for (int i = s; i < e; i++) {
                    int srcn = g_eidx[i];
                    float2 hv = *((const float2*)(X + (size_t)srcn * 64) + lane);
                    acc.x += hv.x;
                    acc.y += hv.y;
                }
            }
            *(float2*)(As + (wid * 16 + j) * AS_STRIDE + 2 * lane) = acc;
        }
        __syncthreads();

        // MMA: accumulate this relation into the persistent register tile
        const int ar0 = wid * 16 + g;
#pragma unroll
        for (int kt = 0; kt < 8; kt++) {
            int kb = kt * 8;
            uint32_t a0 = f2tf32(As[ar0 * AS_STRIDE + kb + t4]);
            uint32_t a1 = f2tf32(As[(ar0 + 8) * AS_STRIDE + kb + t4]);
            uint32_t a2 = f2tf32(As[ar0 * AS_STRIDE + kb + t4 + 4]);
            uint32_t a3 = f2tf32(As[(ar0 + 8) * AS_STRIDE + kb + t4 + 4]);
#pragma unroll
            for (int nt = 0; nt < 8; nt++) {
                int n = nt * 8 + g;
                uint32_t b0 = Ws[(kb + t4) * WS_STRIDE + n];
                uint32_t b1 = Ws[(kb + t4 + 4) * WS_STRIDE + n];
                asm volatile(
                    "mma.sync.aligned.m16n8k8.row.col.f32.tf32.tf32.f32 "
                    "{%0,%1,%2,%3}, {%4,%5,%6,%7}, {%8,%9}, {%0,%1,%2,%3};"
                    : "+f"(c[nt][0]), "+f"(c[nt][1]), "+f"(c[nt][2]), "+f"(c[nt][3])
                    : "r"(a0), "r"(a1), "r"(a2), "r"(a3), "r"(b0), "r"(b1));
            }
        }
    }

    // epilogue: write out tile (relu for hidden layer)
    const int m_lo = m0 + wid * 16 + g;
    const int m_hi = m_lo + 8;
#pragma unroll
    for (int nt = 0; nt < 8; nt++) {
        int col = nt * 8 + t4 * 2;
        float2 lo = make_float2(c[nt][0], c[nt][1]);
        float2 hi = make_float2(c[nt][2], c[nt][3]);
        if (RELU) {
            lo.x = fmaxf(lo.x, 0.f); lo.y = fmaxf(lo.y, 0.f);
            hi.x = fmaxf(hi.x, 0.f); hi.y = fmaxf(hi.y, 0.f);
        }
        if (m_lo < N_NODES) *(float2*)(out + (size_t)m_lo * 64 + col) = lo;
        if (m_hi < N_NODES) *(float2*)(out + (size_t)m_hi * 64 + col) = hi;
    }
}

// ---------------- tail: graph mean + MLP ----------------
__global__ void k_reduce(const float* __restrict__ h2) {
    __shared__ float sm[D_FEAT];
    int t = threadIdx.x;
    if (t < D_FEAT) sm[t] = 0.f;
    __syncthreads();
    float acc = 0.f;
    const long total = (long)N_NODES * D_FEAT;
    for (long i = (long)blockIdx.x * blockDim.x + t; i < total; i += (long)gridDim.x * blockDim.x)
        acc += h2[i];
    atomicAdd(&sm[t & 63], acc);
    __syncthreads();
    if (t < D_FEAT) atomicAdd(&g_sum[t], sm[t]);
}

__global__ void k_mlp(const float* __restrict__ A1w, const float* __restrict__ A1b,
                      const float* __restrict__ A2w, const float* __restrict__ A2b,
                      float* __restrict__ out_a) {
    __shared__ float g[D_FEAT];
    __shared__ float a1[HID_ATTR];
    int t = threadIdx.x;
    if (t < D_FEAT) g[t] = g_sum[t] * (1.0f / (float)N_NODES);
    __syncthreads();
    if (t < HID_ATTR) {
        float s = A1b[t];
#pragma unroll
        for (int k = 0; k < D_FEAT; k++) s += g[k] * A1w[k * HID_ATTR + t];
        a1[t] = fmaxf(s, 0.f);
    }
    __syncthreads();
    if (t < OUT_ATTR) {
        float s = A2b[t];
#pragma unroll
        for (int k = 0; k < HID_ATTR; k++) s += a1[k] * A2w[k * OUT_ATTR + t];
        out_a[t] = 1.0f / (1.0f + expf(-s));
    }
}

// ---------------- launch ----------------
extern "C" void kernel_launch(void* const* d_in, const int* in_sizes, int n_in,
                              void* d_out, int out_size) {
    const float* h     = (const float*)d_in[0];
    const int*   src   = (const int*)d_in[1];
    const int*   dst   = (const int*)d_in[2];
    const int*   etype = (const int*)d_in[3];
    const float* W1    = (const float*)d_in[4];
    const float* W2    = (const float*)d_in[5];
    const float* A1w   = (const float*)d_in[6];
    const float* A1b   = (const float*)d_in[7];
    const float* A2w   = (const float*)d_in[8];
    const float* A2b   = (const float*)d_in[9];
    float* out = (float*)d_out;

    float* H1;  cudaGetSymbolAddress((void**)&H1, g_H1);

    cudaFuncSetAttribute(k_fused<true>,  cudaFuncAttributeMaxDynamicSharedMemorySize, FU_SMEM);
    cudaFuncSetAttribute(k_fused<false>, cudaFuncAttributeMaxDynamicSharedMemorySize, FU_SMEM);

    const int EB = (N_EDGES + 255) / 256;          // 12500
    const int SB = (NSEG + 255) / 256;             // 7813

    // CSR build over (etype, dst) segments
    k_zero<<<SB, 256>>>();
    k_count<<<EB, 256>>>(dst, etype);
    k_scan1<<<SC_BLOCKS, 256>>>();
    k_scan2<<<1, 1024>>>();
    k_scan3<<<SB, 256>>>();
    k_fill<<<EB, 256>>>(src, dst, etype);

    const int TILES = (N_NODES + 127) / 128;       // 782

    // layer 1 (relu) and layer 2 (none), fully fused aggregate+transform
    k_fused<true><<<TILES, 256, FU_SMEM>>>(h, W1, H1);
    k_fused<false><<<TILES, 256, FU_SMEM>>>(H1, W2, out);

    // graph mean + attributor MLP -> last 10 floats of d_out
    k_reduce<<<256, 256>>>(out);
    k_mlp<<<1, 64>>>(A1w, A1b, A2w, A2b, out + (size_t)N_NODES * D_FEAT);
}

// round 5
// speedup vs baseline: 1.2311x; 1.2311x over previous
#include <cuda_runtime.h>
#include <cstdint>
#include <math.h>

#define N_NODES 100000
#define N_EDGES 3200000
#define D_FEAT 64
#define NUM_RELS 20
#define HID_ATTR 32
#define OUT_ATTR 10

#define NSEG (NUM_RELS * N_NODES)          // 2,000,000 segments (r*N + dst)
#define SCAN_CHUNK 1024
#define SC_BLOCKS ((NSEG + SCAN_CHUNK - 1) / SCAN_CHUNK)   // 1954
#define SCAN_PAD (SC_BLOCKS * SCAN_CHUNK)

// ---------------- scratch (device globals; no allocation allowed) ----------------
__device__ float   g_H1[(size_t)N_NODES * D_FEAT];           // hidden layer output
__device__ int     g_cnt[NSEG];
__device__ int     g_fill[NSEG];
__device__ int     g_rowptr[NSEG + 1];
__device__ int     g_scan[SCAN_PAD];
__device__ int     g_bsums[SC_BLOCKS];
__device__ int     g_boff[SC_BLOCKS];
__device__ int     g_eidx[N_EDGES];                          // sorted by (etype,dst): src node id
__device__ uint8_t g_edloc[N_EDGES];                         // dst & 127 (tile-local row)
__device__ float   g_sum[D_FEAT];                            // column sums of h2

__device__ __forceinline__ uint32_t f2tf32(float x) {
    uint32_t r; asm("cvt.rna.tf32.f32 %0, %1;" : "=r"(r) : "f"(x)); return r;
}

// ---------------- CSR build kernels ----------------
__global__ void k_zero() {
    int i = blockIdx.x * blockDim.x + threadIdx.x;
    if (i < NSEG) { g_cnt[i] = 0; g_fill[i] = 0; }
    if (blockIdx.x == 0 && threadIdx.x < D_FEAT) g_sum[threadIdx.x] = 0.0f;
}

__global__ void k_count(const int* __restrict__ dst, const int* __restrict__ etype) {
    int e = blockIdx.x * blockDim.x + threadIdx.x;
    if (e < N_EDGES) atomicAdd(&g_cnt[etype[e] * N_NODES + dst[e]], 1);
}

__global__ void k_scan1() {
    __shared__ int sm[256];
    int t = threadIdx.x;
    int base = blockIdx.x * SCAN_CHUNK;
    int v[4];
    int local = 0;
#pragma unroll
    for (int c = 0; c < 4; c++) {
        int idx = base + t * 4 + c;
        v[c] = (idx < NSEG) ? g_cnt[idx] : 0;
        local += v[c];
    }
    sm[t] = local;
    __syncthreads();
    for (int off = 1; off < 256; off <<= 1) {
        int x = sm[t];
        int y = (t >= off) ? sm[t - off] : 0;
        __syncthreads();
        sm[t] = x + y;
        __syncthreads();
    }
    int run = sm[t] - local;
#pragma unroll
    for (int c = 0; c < 4; c++) {
        run += v[c];
        g_scan[base + t * 4 + c] = run;   // inclusive within chunk
    }
    if (t == 255) g_bsums[blockIdx.x] = sm[255];
}

// scan 1954 block sums with one 1024-thread block (2 elems/thread, ping-pong HS)
__global__ void k_scan2() {
    __shared__ int a[1024], b[1024];
    int t = threadIdx.x;
    int v0 = (2 * t     < SC_BLOCKS) ? g_bsums[2 * t]     : 0;
    int v1 = (2 * t + 1 < SC_BLOCKS) ? g_bsums[2 * t + 1] : 0;
    int pair = v0 + v1;
    a[t] = pair;
    __syncthreads();
    int* cur = a; int* nxt = b;
    for (int off = 1; off < 1024; off <<= 1) {
        int x = cur[t];
        if (t >= off) x += cur[t - off];
        nxt[t] = x;
        __syncthreads();
        int* tmp = cur; cur = nxt; nxt = tmp;
    }
    int excl_pair = cur[t] - pair;     // exclusive scan of pair sums
    if (2 * t     < SC_BLOCKS) g_boff[2 * t]     = excl_pair;
    if (2 * t + 1 < SC_BLOCKS) g_boff[2 * t + 1] = excl_pair + v0;
}

__global__ void k_scan3() {
    int i = blockIdx.x * blockDim.x + threadIdx.x;
    if (i < NSEG) g_rowptr[i + 1] = g_scan[i] + g_boff[i >> 10];
    if (i == 0) g_rowptr[0] = 0;
}

__global__ void k_fill(const int* __restrict__ src, const int* __restrict__ dst,
                       const int* __restrict__ etype) {
    int e = blockIdx.x * blockDim.x + threadIdx.x;
    if (e < N_EDGES) {
        int d = dst[e];
        int key = etype[e] * N_NODES + d;
        int pos = g_rowptr[key] + atomicAdd(&g_fill[key], 1);
        g_eidx[pos] = src[e];
        g_edloc[pos] = (uint8_t)(d & 127);
    }
}

// ---------------- fused layer: out[v] = act( sum_r (sum_{e in r->v} X[src]) @ W[r] )
// CTA = 128 dst nodes (8 warps x 16); accumulator tile in registers across all 20 rels.
// Gather: per warp, flat contiguous edge range per relation; register-accumulate,
// STS-flush on dst change (edges sorted by dst -> each row flushed once, no atomics).
#define AS_STRIDE 68
#define AS_WORDS (128 * AS_STRIDE)          // 34816 B
#define WS_STRIDE 72
#define WS_WORDS (64 * WS_STRIDE)           // 18432 B
#define FU_SMEM ((AS_WORDS + WS_WORDS) * 4) // 53248 B

template <bool RELU>
__global__ void __launch_bounds__(256) k_fused(const float* __restrict__ X,
                                               const float* __restrict__ W,
                                               float* __restrict__ out) {
    extern __shared__ float smf[];
    float*    As = smf;                            // f32  [128][68]
    uint32_t* Ws = (uint32_t*)(smf + AS_WORDS);    // tf32 [64][72]

    const int tid = threadIdx.x;
    const int wid = tid >> 5;
    const int lane = tid & 31;
    const int g = lane >> 2;             // groupID 0..7
    const int t4 = lane & 3;             // thread-in-group 0..3
    const int m0 = blockIdx.x * 128;
    const int base = m0 + wid * 16;      // this warp's 16 dst nodes
    const int nb = max(0, min(16, N_NODES - base));   // valid nodes in this warp's span

    float c[8][4];
#pragma unroll
    for (int nt = 0; nt < 8; nt++) { c[nt][0] = 0.f; c[nt][1] = 0.f; c[nt][2] = 0.f; c[nt][3] = 0.f; }

    for (int r = 0; r < NUM_RELS; r++) {
        if (r) __syncthreads();          // prior MMA's Ws reads done; safe to overwrite Ws

        // stage W[r] as tf32 [k][n] (B col-major for row.col mma)
        const float* Wr = W + (size_t)r * 4096;
#pragma unroll
        for (int i = 0; i < 4; i++) {
            int f = i * 256 + tid;       // float4 slot 0..1023
            int krow = f >> 4;
            int n4 = (f & 15) << 2;
            float4 v = *(const float4*)(Wr + krow * 64 + n4);
            uint4 u;
            u.x = f2tf32(v.x); u.y = f2tf32(v.y); u.z = f2tf32(v.z); u.w = f2tf32(v.w);
            *(uint4*)(Ws + krow * WS_STRIDE + n4) = u;
        }

        // zero this warp's 16 As rows (warp-private: no sync needed)
#pragma unroll
        for (int j = 0; j < 16; j++)
            *(float2*)(As + (wid * 16 + j) * AS_STRIDE + 2 * lane) = make_float2(0.f, 0.f);

        // flat edge range for (relation r, nodes [base, base+nb))
        if (nb > 0) {
            int s = g_rowptr[r * N_NODES + base];
            int e = g_rowptr[r * N_NODES + base + nb];
            float2 acc = make_float2(0.f, 0.f);
            int cur = -1;
            for (int i = s; i < e; i++) {
                int srcn = g_eidx[i];          // uniform across warp
                int dl = (int)g_edloc[i];      // tile-local row, uniform
                if (dl != cur) {
                    if (cur >= 0)
                        *(float2*)(As + cur * AS_STRIDE + 2 * lane) = acc;
                    cur = dl;
                    acc = make_float2(0.f, 0.f);
                }
                float2 hv = *((const float2*)(X + (size_t)srcn * 64) + lane);
                acc.x += hv.x;
                acc.y += hv.y;
            }
            if (cur >= 0)
                *(float2*)(As + cur * AS_STRIDE + 2 * lane) = acc;
        }
        __syncthreads();                 // Ws staged (and all As rows written)

        // MMA: accumulate this relation into the persistent register tile
        const int ar0 = wid * 16 + g;
#pragma unroll
        for (int kt = 0; kt < 8; kt++) {
            int kb = kt * 8;
            uint32_t a0 = f2tf32(As[ar0 * AS_STRIDE + kb + t4]);
            uint32_t a1 = f2tf32(As[(ar0 + 8) * AS_STRIDE + kb + t4]);
            uint32_t a2 = f2tf32(As[ar0 * AS_STRIDE + kb + t4 + 4]);
            uint32_t a3 = f2tf32(As[(ar0 + 8) * AS_STRIDE + kb + t4 + 4]);
#pragma unroll
            for (int nt = 0; nt < 8; nt++) {
                int n = nt * 8 + g;
                uint32_t b0 = Ws[(kb + t4) * WS_STRIDE + n];
                uint32_t b1 = Ws[(kb + t4 + 4) * WS_STRIDE + n];
                asm volatile(
                    "mma.sync.aligned.m16n8k8.row.col.f32.tf32.tf32.f32 "
                    "{%0,%1,%2,%3}, {%4,%5,%6,%7}, {%8,%9}, {%0,%1,%2,%3};"
                    : "+f"(c[nt][0]), "+f"(c[nt][1]), "+f"(c[nt][2]), "+f"(c[nt][3])
                    : "r"(a0), "r"(a1), "r"(a2), "r"(a3), "r"(b0), "r"(b1));
            }
        }
    }

    // epilogue: write out tile (relu for hidden layer)
    const int m_lo = m0 + wid * 16 + g;
    const int m_hi = m_lo + 8;
#pragma unroll
    for (int nt = 0; nt < 8; nt++) {
        int col = nt * 8 + t4 * 2;
        float2 lo = make_float2(c[nt][0], c[nt][1]);
        float2 hi = make_float2(c[nt][2], c[nt][3]);
        if (RELU) {
            lo.x = fmaxf(lo.x, 0.f); lo.y = fmaxf(lo.y, 0.f);
            hi.x = fmaxf(hi.x, 0.f); hi.y = fmaxf(hi.y, 0.f);
        }
        if (m_lo < N_NODES) *(float2*)(out + (size_t)m_lo * 64 + col) = lo;
        if (m_hi < N_NODES) *(float2*)(out + (size_t)m_hi * 64 + col) = hi;
    }
}

// ---------------- tail: graph mean + MLP ----------------
__global__ void k_reduce(const float* __restrict__ h2) {
    __shared__ float sm[D_FEAT];
    int t = threadIdx.x;
    if (t < D_FEAT) sm[t] = 0.f;
    __syncthreads();
    float acc = 0.f;
    const long total = (long)N_NODES * D_FEAT;
    for (long i = (long)blockIdx.x * blockDim.x + t; i < total; i += (long)gridDim.x * blockDim.x)
        acc += h2[i];
    atomicAdd(&sm[t & 63], acc);
    __syncthreads();
    if (t < D_FEAT) atomicAdd(&g_sum[t], sm[t]);
}

__global__ void k_mlp(const float* __restrict__ A1w, const float* __restrict__ A1b,
                      const float* __restrict__ A2w, const float* __restrict__ A2b,
                      float* __restrict__ out_a) {
    __shared__ float g[D_FEAT];
    __shared__ float a1[HID_ATTR];
    int t = threadIdx.x;
    if (t < D_FEAT) g[t] = g_sum[t] * (1.0f / (float)N_NODES);
    __syncthreads();
    if (t < HID_ATTR) {
        float s = A1b[t];
#pragma unroll
        for (int k = 0; k < D_FEAT; k++) s += g[k] * A1w[k * HID_ATTR + t];
        a1[t] = fmaxf(s, 0.f);
    }
    __syncthreads();
    if (t < OUT_ATTR) {
        float s = A2b[t];
#pragma unroll
        for (int k = 0; k < HID_ATTR; k++) s += a1[k] * A2w[k * OUT_ATTR + t];
        out_a[t] = 1.0f / (1.0f + expf(-s));
    }
}

// ---------------- launch ----------------
extern "C" void kernel_launch(void* const* d_in, const int* in_sizes, int n_in,
                              void* d_out, int out_size) {
    const float* h     = (const float*)d_in[0];
    const int*   src   = (const int*)d_in[1];
    const int*   dst   = (const int*)d_in[2];
    const int*   etype = (const int*)d_in[3];
    const float* W1    = (const float*)d_in[4];
    const float* W2    = (const float*)d_in[5];
    const float* A1w   = (const float*)d_in[6];
    const float* A1b   = (const float*)d_in[7];
    const float* A2w   = (const float*)d_in[8];
    const float* A2b   = (const float*)d_in[9];
    float* out = (float*)d_out;

    float* H1;  cudaGetSymbolAddress((void**)&H1, g_H1);

    cudaFuncSetAttribute(k_fused<true>,  cudaFuncAttributeMaxDynamicSharedMemorySize, FU_SMEM);
    cudaFuncSetAttribute(k_fused<false>, cudaFuncAttributeMaxDynamicSharedMemorySize, FU_SMEM);

    const int EB = (N_EDGES + 255) / 256;          // 12500
    const int SB = (NSEG + 255) / 256;             // 7813

    // CSR build over (etype, dst) segments
    k_zero<<<SB, 256>>>();
    k_count<<<EB, 256>>>(dst, etype);
    k_scan1<<<SC_BLOCKS, 256>>>();
    k_scan2<<<1, 1024>>>();
    k_scan3<<<SB, 256>>>();
    k_fill<<<EB, 256>>>(src, dst, etype);

    const int TILES = (N_NODES + 127) / 128;       // 782

    // layer 1 (relu) and layer 2 (none), fully fused aggregate+transform
    k_fused<true><<<TILES, 256, FU_SMEM>>>(h, W1, H1);
    k_fused<false><<<TILES, 256, FU_SMEM>>>(H1, W2, out);

    // graph mean + attributor MLP -> last 10 floats of d_out
    k_reduce<<<256, 256>>>(out);
    k_mlp<<<1, 64>>>(A1w, A1b, A2w, A2b, out + (size_t)N_NODES * D_FEAT);
}